// round 15
// baseline (speedup 1.0000x reference)
#include <cuda_runtime.h>
#include <cuda_bf16.h>
#include <math.h>
#include <stdint.h>

#define Bn      2
#define Dm      2048
#define Lseq    4096
#define C3D     6144
#define NF      8192
#define HF      4096
#define FO      64

// ------------------- scratch (device globals: no allocs allowed) -------------------
__device__ float g_U [(size_t)Bn * Lseq * C3D];   // in_proj output, (b, l, c)
__device__ float g_VG[(size_t)Bn * Dm * Lseq];    // v * x1, (b, d, l)
__device__ float g_X0[(size_t)Bn * Dm * Lseq];    // x0 gate, (b, d, l)
__device__ float g_H [(size_t)Lseq * FO];         // MLP features (l, j)
__device__ float g_K [(size_t)Dm * Lseq];         // filter k (d, l)
__device__ float g_Y [(size_t)Bn * Dm * Lseq];    // gated conv output, (b, d, l)

// bf16 hi/lo split operands for tensor-core GEMMs
__device__ __nv_bfloat16 g_xh [(size_t)Bn * Lseq * Dm];
__device__ __nv_bfloat16 g_xl [(size_t)Bn * Lseq * Dm];
__device__ __nv_bfloat16 g_wih[(size_t)C3D * Dm];
__device__ __nv_bfloat16 g_wil[(size_t)C3D * Dm];
__device__ __nv_bfloat16 g_woh[(size_t)Dm * Dm];
__device__ __nv_bfloat16 g_wol[(size_t)Dm * Dm];
__device__ __nv_bfloat16 g_yth[(size_t)Bn * Lseq * Dm];
__device__ __nv_bfloat16 g_ytl[(size_t)Bn * Lseq * Dm];

// ------------------- PTX helpers (all legal on compute_103 virtual arch) -------------------
__device__ __forceinline__ uint32_t smem_u32(const void* p) {
    uint32_t a;
    asm("{ .reg .u64 t; cvta.to.shared.u64 t, %1; cvt.u32.u64 %0, t; }" : "=r"(a) : "l"(p));
    return a;
}
__device__ __forceinline__ void cp_async16(uint32_t s, const void* g) {
    asm volatile("cp.async.cg.shared.global [%0], [%1], 16;" :: "r"(s), "l"(g));
}
__device__ __forceinline__ void cp_commit() {
    asm volatile("cp.async.commit_group;");
}
template<int N> __device__ __forceinline__ void cp_wait() {
    asm volatile("cp.async.wait_group %0;" :: "n"(N));
}
__device__ __forceinline__ void ldmx4(uint32_t a, uint32_t* r) {
    asm volatile("ldmatrix.sync.aligned.m8n8.x4.shared.b16 {%0,%1,%2,%3}, [%4];"
                 : "=r"(r[0]), "=r"(r[1]), "=r"(r[2]), "=r"(r[3]) : "r"(a));
}
__device__ __forceinline__ void mma16816(float* d, const uint32_t* a, const uint32_t* b) {
    asm volatile(
        "mma.sync.aligned.m16n8k16.row.col.f32.bf16.bf16.f32 "
        "{%0,%1,%2,%3}, {%4,%5,%6,%7}, {%8,%9}, {%0,%1,%2,%3};"
        : "+f"(d[0]), "+f"(d[1]), "+f"(d[2]), "+f"(d[3])
        : "r"(a[0]), "r"(a[1]), "r"(a[2]), "r"(a[3]), "r"(b[0]), "r"(b[1]));
}
__device__ __forceinline__ uint32_t bf2u(__nv_bfloat162 h) {
    return *reinterpret_cast<uint32_t*>(&h);
}

// ------------------- fp32 -> bf16 hi/lo split (elementwise) -------------------
__global__ __launch_bounds__(256) void conv_hl_kernel(
    const float4* __restrict__ in, uint2* __restrict__ h, uint2* __restrict__ l, int n4)
{
    int i = blockIdx.x * 256 + threadIdx.x;
    if (i >= n4) return;
    float4 v = in[i];
    __nv_bfloat162 h01 = __float22bfloat162_rn(make_float2(v.x, v.y));
    __nv_bfloat162 h23 = __float22bfloat162_rn(make_float2(v.z, v.w));
    float2 f01 = __bfloat1622float2(h01);
    float2 f23 = __bfloat1622float2(h23);
    __nv_bfloat162 l01 = __float22bfloat162_rn(make_float2(v.x - f01.x, v.y - f01.y));
    __nv_bfloat162 l23 = __float22bfloat162_rn(make_float2(v.z - f23.x, v.w - f23.y));
    h[i] = make_uint2(bf2u(h01), bf2u(h23));
    l[i] = make_uint2(bf2u(l01), bf2u(l23));
}

// ------------------- split-bf16 HMMA GEMM (R9 structure + pass-major MMA order) -------------------
// C[m,n] = sum_k A[m,k]*Bw[n,k] + bias[n] with A ~ Ah+Al, Bw ~ Bh+Bl (bf16).
// BM=BN=128, BK=32, 8 warps (2m x 4n), warp tile 64x32, 2-stage cp.async pipeline,
// 81920B smem/CTA -> 2 CTAs/SM. Stage (40960B): Ah[128x32 pad80], Al, Bh, Bl.
__global__ __launch_bounds__(256, 2) void mma_gemm(
    const __nv_bfloat16* __restrict__ Ah, const __nv_bfloat16* __restrict__ Al,
    const __nv_bfloat16* __restrict__ Bh, const __nv_bfloat16* __restrict__ Bl,
    const float* __restrict__ bias, float* __restrict__ C,
    int M, int N, int K)
{
    extern __shared__ char sm[];
    uint32_t smb = smem_u32(sm);
    int tid = threadIdx.x, lid = tid & 31, wid = tid >> 5;
    int wm = wid & 1, wn = wid >> 1;
    int m0 = blockIdx.y * 128, n0 = blockIdx.x * 128;

    const __nv_bfloat16* pAh = Ah + (size_t)m0 * K;
    const __nv_bfloat16* pAl = Al + (size_t)m0 * K;
    const __nv_bfloat16* pBh = Bh + (size_t)n0 * K;
    const __nv_bfloat16* pBl = Bl + (size_t)n0 * K;
    const int nch = K >> 5;

    auto issue = [&](int c) {
        uint32_t sb = smb + (uint32_t)(c & 1) * 40960u;
        #pragma unroll
        for (int t = 0; t < 2; t++) {
            int e = tid + t * 256;
            int row = e >> 2, seg = e & 3;
            size_t go = (size_t)row * K + (size_t)c * 32 + seg * 8;
            uint32_t so = (uint32_t)row * 80u + (uint32_t)seg * 16u;
            cp_async16(sb + so,           pAh + go);
            cp_async16(sb + 10240u + so,  pAl + go);
            cp_async16(sb + 20480u + so,  pBh + go);
            cp_async16(sb + 30720u + so,  pBl + go);
        }
    };

    issue(0); cp_commit();
    if (nch > 1) { issue(1); cp_commit(); }

    float acc[4][4][4];
    #pragma unroll
    for (int mi = 0; mi < 4; mi++)
        #pragma unroll
        for (int ni = 0; ni < 4; ni++)
            #pragma unroll
            for (int q = 0; q < 4; q++) acc[mi][ni][q] = 0.f;

    uint32_t aOff = (uint32_t)(wm * 64 + (lid & 15)) * 80u + (uint32_t)(lid >> 4) * 16u;
    // B ldmx4 lane mapping: row-in-tile = lid&7, +8 rows if lid>=16, k-half if bit3
    uint32_t bOff = 20480u
                  + (uint32_t)(wn * 32 + (lid & 7) + ((lid >> 4) & 1) * 8) * 80u
                  + (uint32_t)((lid >> 3) & 1) * 16u;

    for (int c = 0; c < nch; c++) {
        cp_wait<1>();
        __syncthreads();
        uint32_t sb = smb + (uint32_t)(c & 1) * 40960u;
        #pragma unroll
        for (int ks = 0; ks < 2; ks++) {
            uint32_t ah[4][4], al[4][4], bh[4][2], bl[4][2];
            // B fragments first (small; latency hides under A loads + MMAs)
            #pragma unroll
            for (int p = 0; p < 2; p++) {
                uint32_t a = sb + bOff + (uint32_t)p * 1280u + (uint32_t)ks * 32u;
                uint32_t r[4];
                ldmx4(a, r);
                bh[2*p][0] = r[0]; bh[2*p][1] = r[1]; bh[2*p+1][0] = r[2]; bh[2*p+1][1] = r[3];
                ldmx4(a + 10240u, r);
                bl[2*p][0] = r[0]; bl[2*p][1] = r[1]; bl[2*p+1][0] = r[2]; bl[2*p+1][1] = r[3];
            }
            #pragma unroll
            for (int mi = 0; mi < 4; mi++) {
                uint32_t a = sb + aOff + (uint32_t)mi * 1280u + (uint32_t)ks * 32u;
                ldmx4(a, ah[mi]);
                ldmx4(a + 10240u, al[mi]);
            }
            // pass-major: same-accumulator MMAs separated by 16 ops -> RAW latency hidden
            #pragma unroll
            for (int mi = 0; mi < 4; mi++)
                #pragma unroll
                for (int ni = 0; ni < 4; ni++) mma16816(acc[mi][ni], ah[mi], bh[ni]);
            #pragma unroll
            for (int mi = 0; mi < 4; mi++)
                #pragma unroll
                for (int ni = 0; ni < 4; ni++) mma16816(acc[mi][ni], ah[mi], bl[ni]);
            #pragma unroll
            for (int mi = 0; mi < 4; mi++)
                #pragma unroll
                for (int ni = 0; ni < 4; ni++) mma16816(acc[mi][ni], al[mi], bh[ni]);
        }
        __syncthreads();
        if (c + 2 < nch) issue(c + 2);
        cp_commit();
    }

    // epilogue
    #pragma unroll
    for (int mi = 0; mi < 4; mi++) {
        int r = m0 + wm * 64 + mi * 16 + (lid >> 2);
        #pragma unroll
        for (int ni = 0; ni < 4; ni++) {
            int cc = n0 + wn * 32 + ni * 8 + (lid & 3) * 2;
            float2 bv = *(const float2*)(bias + cc);
            float2 o0 = make_float2(acc[mi][ni][0] + bv.x, acc[mi][ni][1] + bv.y);
            float2 o1 = make_float2(acc[mi][ni][2] + bv.x, acc[mi][ni][3] + bv.y);
            *(float2*)(C + (size_t)r * N + cc)       = o0;
            *(float2*)(C + (size_t)(r + 8) * N + cc) = o1;
        }
    }
}

// ------------------- transpose (b,d,l) -> (b,l,d), fused bf16 hi/lo split -------------------
__global__ __launch_bounds__(256) void transpose_hl_kernel(
    const float* __restrict__ Y, __nv_bfloat16* __restrict__ Th, __nv_bfloat16* __restrict__ Tl)
{
    __shared__ float ts[32][33];
    int b = blockIdx.z;
    int d0 = blockIdx.y * 32, l0 = blockIdx.x * 32;
    int c = threadIdx.x & 31, r0 = threadIdx.x >> 5;
    #pragma unroll
    for (int p = 0; p < 4; p++) {
        int r = r0 + p * 8;
        ts[r][c] = Y[((size_t)b * Dm + d0 + r) * Lseq + l0 + c];
    }
    __syncthreads();
    #pragma unroll
    for (int p = 0; p < 4; p++) {
        int r = r0 + p * 8;
        float v = ts[c][r];
        __nv_bfloat16 h = __float2bfloat16_rn(v);
        __nv_bfloat16 l = __float2bfloat16_rn(v - __bfloat162float(h));
        size_t o = ((size_t)b * Lseq + l0 + r) * Dm + d0 + c;
        Th[o] = h;
        Tl[o] = l;
    }
}

// ------------------- complex helpers -------------------
__device__ __forceinline__ float2 cadd(float2 a, float2 b) { return make_float2(a.x+b.x, a.y+b.y); }
__device__ __forceinline__ float2 csub(float2 a, float2 b) { return make_float2(a.x-b.x, a.y-b.y); }
__device__ __forceinline__ float2 cmul(float2 a, float2 b) {
    return make_float2(a.x*b.x - a.y*b.y, a.x*b.y + a.y*b.x);
}
__device__ __forceinline__ float2 cmulc(float2 a, float2 b) {  // a * conj(b)
    return make_float2(a.x*b.x + a.y*b.y, a.y*b.x - a.x*b.y);
}

// ------------------- short depthwise conv (K=3, causal) + split + gate -------------------
__global__ __launch_bounds__(256) void shortconv_kernel(
    const float* __restrict__ U, const float* __restrict__ sw,
    const float* __restrict__ sb, float* __restrict__ VG, float* __restrict__ X0)
{
    __shared__ float su[3][66][33];
    int tid = threadIdx.x;
    int b = blockIdx.z, d0 = blockIdx.y * 32, l0 = blockIdx.x * 64;

    for (int idx = tid; idx < 3*66*32; idx += 256) {
        int d = idx & 31;
        int rest = idx >> 5;
        int x = rest % 66;
        int g = rest / 66;
        int l = l0 - 2 + x;
        float v = 0.f;
        if (l >= 0) v = U[((size_t)b * Lseq + l) * C3D + g * Dm + d0 + d];
        su[g][x][d] = v;
    }
    __syncthreads();

    int l = tid & 63;
    int dq = tid >> 6;
    #pragma unroll
    for (int p = 0; p < 8; p++) {
        int dloc = dq + (p << 2);
        int c0 = d0 + dloc;
        float r[3];
        #pragma unroll
        for (int g = 0; g < 3; g++) {
            int c = g * Dm + c0;
            float w0 = sw[c*3+0], w1 = sw[c*3+1], w2 = sw[c*3+2];
            r[g] = w0 * su[g][l][dloc] + w1 * su[g][l+1][dloc] + w2 * su[g][l+2][dloc] + sb[c];
        }
        size_t o = ((size_t)b * Dm + c0) * Lseq + l0 + l;
        X0[o] = r[0];
        VG[o] = r[2] * r[1];
    }
}

// ------------------- filter MLP features h (L, 64) -------------------
__global__ __launch_bounds__(256) void filter_h_kernel(
    const float* __restrict__ w0, const float* __restrict__ b0,
    const float* __restrict__ freq,
    const float* __restrict__ w1, const float* __restrict__ b1,
    const float* __restrict__ w2, const float* __restrict__ b2)
{
    int l = blockIdx.x * blockDim.x + threadIdx.x;
    if (l >= Lseq) return;
    const float PI2 = 6.2831853071795864769f;
    float t  = (float)l / (float)(Lseq - 1);
    float wl = PI2 * (float)l / (float)Lseq;
    float ang = 1e-4f * wl;
    float z0 = t, z1 = cosf(ang), z2 = -sinf(ang);

    float h0[FO], h1[FO], h2[FO];
    #pragma unroll
    for (int j = 0; j < FO; j++) {
        float s = w0[j*3+0]*z0 + w0[j*3+1]*z1 + w0[j*3+2]*z2 + b0[j];
        h0[j] = sinf(freq[j] * s);
    }
    #pragma unroll
    for (int j = 0; j < FO; j++) {
        float s = b1[j];
        #pragma unroll
        for (int q = 0; q < FO; q++) s += h0[q] * w1[j*FO+q];
        h1[j] = sinf(freq[j] * s);
    }
    #pragma unroll
    for (int j = 0; j < FO; j++) {
        float s = b2[j];
        #pragma unroll
        for (int q = 0; q < FO; q++) s += h1[q] * w2[j*FO+q];
        h2[j] = sinf(freq[j] * s);
    }
    #pragma unroll
    for (int j = 0; j < FO; j++) g_H[(size_t)l*FO + j] = h2[j];
}

// ------------------- filter k(d,l) = (h @ w3^T) * decay, register-blocked -------------------
__global__ __launch_bounds__(256) void filter_k_kernel(const float* __restrict__ w3)
{
    __shared__ float HtT[FO][66];    // HtT[j][l_local]
    __shared__ float W3T[FO][68];    // W3T[j][d_local]
    int d0 = blockIdx.x * 64, l0 = blockIdx.y * 64;
    int tid = threadIdx.x;

    for (int idx = tid; idx < 64*FO; idx += 256) {
        int l = idx >> 6, j = idx & 63;
        HtT[j][l] = g_H[(size_t)(l0 + l)*FO + j];
    }
    for (int idx = tid; idx < 64*FO; idx += 256) {
        int d = idx >> 6, j = idx & 63;
        W3T[j][d] = w3[(size_t)(d0 + d)*FO + j];
    }
    __syncthreads();

    int lg = tid >> 3;   // 0..31 -> 2 l's each
    int dg = tid & 7;    // 0..7  -> 8 d's each
    float acc[2][8];
    #pragma unroll
    for (int a = 0; a < 2; a++)
        #pragma unroll
        for (int b = 0; b < 8; b++) acc[a][b] = 0.f;

    #pragma unroll 4
    for (int j = 0; j < FO; j++) {
        float2 h2v = *(const float2*)&HtT[j][lg*2];
        float4 wv0 = *(const float4*)&W3T[j][dg*8];
        float4 wv1 = *(const float4*)&W3T[j][dg*8 + 4];
        float wv[8] = {wv0.x, wv0.y, wv0.z, wv0.w, wv1.x, wv1.y, wv1.z, wv1.w};
        float hv[2] = {h2v.x, h2v.y};
        #pragma unroll
        for (int a = 0; a < 2; a++)
            #pragma unroll
            for (int b = 0; b < 8; b++) acc[a][b] += hv[a] * wv[b];
    }

    const float MIN_DEC = -3.0701134573253944f;   // log(0.01)/1.5
    const float MAX_DEC = -15.350567286626972f;   // log(0.01)/0.3
    #pragma unroll
    for (int a = 0; a < 2; a++) {
        int l = l0 + lg*2 + a;
        float t = (float)l / (float)(Lseq - 1);
        #pragma unroll
        for (int b = 0; b < 8; b++) {
            int d = d0 + dg*8 + b;
            float delta = MIN_DEC + (MAX_DEC - MIN_DEC) * ((float)d / (float)(Dm - 1));
            float decay = __expf(-t * fabsf(delta));
            g_K[(size_t)d * Lseq + l] = acc[a][b] * decay;
        }
    }
}

// ------------------- radix-4 FFT causal conv, fused gating -------------------
// Forward DIF (natural -> base-4-digit-reversed), product in permuted order,
// inverse DIT (permuted -> natural). First fwd stage folded into zero-padded
// load; last inv stage folded into epilogue; the middle (final fwd radix-2 of
// W and KF + pointwise product + first inverse radix-2) fused into ONE pass.

template<int M>
__device__ __forceinline__ void r4f(float2* X, const float2* TW, int tid)
{
    const int T = 2048 / M;
    #pragma unroll
    for (int it = 0; it < 4; it++) {
        int i = tid + it * 512;
        int j = i & (M - 1);
        int b0 = (i / M) * (4 * M) + j;
        float2 a = X[b0], b = X[b0 + M], c = X[b0 + 2*M], d = X[b0 + 3*M];
        float2 s0 = cadd(a, c), s1 = csub(a, c);
        float2 s2 = cadd(b, d), s3 = csub(b, d);
        float2 t3 = make_float2(s3.y, -s3.x);           // -i * s3
        float2 w1 = TW[j * T], w2 = TW[2 * j * T];
        float2 w3 = cmul(w1, w2);
        X[b0]       = cadd(s0, s2);
        X[b0 + M]   = cmul(cadd(s1, t3), w1);
        X[b0 + 2*M] = cmul(csub(s0, s2), w2);
        X[b0 + 3*M] = cmul(csub(s1, t3), w3);
    }
    __syncthreads();
}

template<int M>
__device__ __forceinline__ void r4i(float2* X, const float2* TW, int tid)
{
    const int T = 2048 / M;
    #pragma unroll
    for (int it = 0; it < 4; it++) {
        int i = tid + it * 512;
        int j = i & (M - 1);
        int b0 = (i / M) * (4 * M) + j;
        float2 w1 = TW[j * T], w2 = TW[2 * j * T];
        float2 w3 = cmul(w1, w2);
        float2 u0 = X[b0];
        float2 u1 = cmulc(X[b0 + M],   w1);
        float2 u2 = cmulc(X[b0 + 2*M], w2);
        float2 u3 = cmulc(X[b0 + 3*M], w3);
        float2 p0 = cadd(u0, u2), p1 = csub(u0, u2);
        float2 q0 = cadd(u1, u3), q1 = csub(u1, u3);
        float2 iq1 = make_float2(-q1.y, q1.x);          // +i * q1
        X[b0]       = cadd(p0, q0);
        X[b0 + M]   = cadd(p1, iq1);
        X[b0 + 2*M] = csub(p0, q0);
        X[b0 + 3*M] = csub(p1, iq1);
    }
    __syncthreads();
}

__global__ __launch_bounds__(512) void fftconv_kernel(
    const float* __restrict__ VG, const float* __restrict__ X0g,
    const float* __restrict__ Kf, const float* __restrict__ fbias,
    float* __restrict__ Y)
{
    extern __shared__ float2 smf[];
    float2* W  = smf;                // 8192
    float2* KF = smf + NF;           // 8192
    float2* TW = smf + 2*NF;         // 4096

    int d = blockIdx.x, tid = threadIdx.x;

    for (int j = tid; j < HF; j += 512) {
        float s, c;
        sincosf(-6.283185307179586f * ((float)j * (1.0f / (float)NF)), &s, &c);
        TW[j] = make_float2(c, s);
    }
    __syncthreads();

    // load + first forward radix-4 stage (span 2048; upper half zero)
    const float* kd  = Kf + (size_t)d * Lseq;
    const float* vg0 = VG + (size_t)d * Lseq;
    const float* vg1 = VG + ((size_t)Dm + d) * Lseq;
    for (int j = tid; j < 2048; j += 512) {
        float2 w1 = TW[j], w2 = TW[2*j];
        float2 w3 = cmul(w1, w2);
        float k0 = kd[j], k1 = kd[j + 2048];
        KF[j]        = make_float2(k0 + k1, 0.f);
        KF[j + 2048] = cmul(make_float2(k0, -k1), w1);
        KF[j + 4096] = make_float2((k0 - k1) * w2.x, (k0 - k1) * w2.y);
        KF[j + 6144] = cmul(make_float2(k0, k1), w3);
        float2 a0 = make_float2(vg0[j], vg1[j]);
        float2 a1 = make_float2(vg0[j + 2048], vg1[j + 2048]);
        float2 mia1 = make_float2(a1.y, -a1.x);   // -i*a1
        float2 pia1 = make_float2(-a1.y, a1.x);   // +i*a1
        W[j]        = cadd(a0, a1);
        W[j + 2048] = cmul(cadd(a0, mia1), w1);
        W[j + 4096] = cmul(csub(a0, a1), w2);
        W[j + 6144] = cmul(cadd(a0, pia1), w3);
    }
    __syncthreads();

    // forward radix-4 stages (KF then W); final radix-2 deferred to fused middle
    r4f<512>(KF, TW, tid); r4f<128>(KF, TW, tid); r4f<32>(KF, TW, tid);
    r4f<8>(KF, TW, tid);   r4f<2>(KF, TW, tid);

    r4f<512>(W, TW, tid); r4f<128>(W, TW, tid); r4f<32>(W, TW, tid);
    r4f<8>(W, TW, tid);   r4f<2>(W, TW, tid);

    // FUSED middle: final fwd radix-2 (W and KF, in registers) + pointwise
    // product + first inverse radix-2 — one smem pass instead of four.
    #pragma unroll
    for (int it = 0; it < 8; it++) {
        int i = tid + it * 512;
        int b = i << 1;
        float2 a = W[b], c = W[b + 1];
        float2 u = cadd(a, c), v = csub(a, c);
        float2 ka = KF[b], kc = KF[b + 1];
        float2 k0 = cadd(ka, kc), k1 = csub(ka, kc);
        float2 p0 = cmul(u, k0), p1 = cmul(v, k1);
        W[b]     = cadd(p0, p1);
        W[b + 1] = csub(p0, p1);
    }
    __syncthreads();

    // inverse radix-4 stages
    r4i<2>(W, TW, tid);  r4i<8>(W, TW, tid);   r4i<32>(W, TW, tid);
    r4i<128>(W, TW, tid); r4i<512>(W, TW, tid);

    // final inverse stage (span 2048) fused with gating epilogue
    float bd = fbias[d];
    const float* x00 = X0g + (size_t)d * Lseq;
    const float* x01 = X0g + ((size_t)Dm + d) * Lseq;
    float* y0 = Y + (size_t)d * Lseq;
    float* y1 = Y + ((size_t)Dm + d) * Lseq;
    const float inv = 1.0f / (float)NF;
    for (int j = tid; j < 2048; j += 512) {
        float2 w1 = TW[j], w2 = TW[2*j];
        float2 w3 = cmul(w1, w2);
        float2 u0 = W[j];
        float2 u1 = cmulc(W[j + 2048], w1);
        float2 u2 = cmulc(W[j + 4096], w2);
        float2 u3 = cmulc(W[j + 6144], w3);
        float2 x0v = cadd(cadd(u0, u1), cadd(u2, u3));
        float2 p1 = csub(u0, u2), q1 = csub(u1, u3);
        float2 x1v = make_float2(p1.x - q1.y, p1.y + q1.x);
        int l0i = j, l1i = j + 2048;
        y0[l0i] = (x0v.x * inv + vg0[l0i] * bd) * x00[l0i];
        y1[l0i] = (x0v.y * inv + vg1[l0i] * bd) * x01[l0i];
        y0[l1i] = (x1v.x * inv + vg0[l1i] * bd) * x00[l1i];
        y1[l1i] = (x1v.y * inv + vg1[l1i] * bd) * x01[l1i];
    }
}

// ------------------- launch -------------------
extern "C" void kernel_launch(void* const* d_in, const int* in_sizes, int n_in,
                              void* d_out, int out_size)
{
    const float* x       = (const float*)d_in[0];
    const float* in_w    = (const float*)d_in[1];
    const float* in_b    = (const float*)d_in[2];
    const float* short_w = (const float*)d_in[3];
    const float* short_b = (const float*)d_in[4];
    const float* w0      = (const float*)d_in[5];
    const float* b0      = (const float*)d_in[6];
    const float* freq    = (const float*)d_in[7];
    const float* w1      = (const float*)d_in[8];
    const float* b1      = (const float*)d_in[9];
    const float* w2      = (const float*)d_in[10];
    const float* b2      = (const float*)d_in[11];
    const float* w3      = (const float*)d_in[12];
    const float* fbias   = (const float*)d_in[13];
    const float* out_w   = (const float*)d_in[14];
    const float* out_b   = (const float*)d_in[15];
    float* out = (float*)d_out;

    float *pU, *pVG, *pX0, *pK, *pY;
    __nv_bfloat16 *pxh, *pxl, *pwih, *pwil, *pwoh, *pwol, *pyth, *pytl;
    cudaGetSymbolAddress((void**)&pU,   g_U);
    cudaGetSymbolAddress((void**)&pVG,  g_VG);
    cudaGetSymbolAddress((void**)&pX0,  g_X0);
    cudaGetSymbolAddress((void**)&pK,   g_K);
    cudaGetSymbolAddress((void**)&pY,   g_Y);
    cudaGetSymbolAddress((void**)&pxh,  g_xh);
    cudaGetSymbolAddress((void**)&pxl,  g_xl);
    cudaGetSymbolAddress((void**)&pwih, g_wih);
    cudaGetSymbolAddress((void**)&pwil, g_wil);
    cudaGetSymbolAddress((void**)&pwoh, g_woh);
    cudaGetSymbolAddress((void**)&pwol, g_wol);
    cudaGetSymbolAddress((void**)&pyth, g_yth);
    cudaGetSymbolAddress((void**)&pytl, g_ytl);

    const int GEMM_SMEM = 2 * 40960;   // 81920 -> 2 CTAs/SM
    cudaFuncSetAttribute(mma_gemm, cudaFuncAttributeMaxDynamicSharedMemorySize, GEMM_SMEM);
    cudaFuncSetAttribute(fftconv_kernel, cudaFuncAttributeMaxDynamicSharedMemorySize, 163840);

    // 0) split fp32 -> bf16 hi/lo for GEMM operands
    {
        int n4;
        n4 = (Bn * Lseq * Dm) / 4;
        conv_hl_kernel<<<(n4 + 255) / 256, 256>>>((const float4*)x, (uint2*)pxh, (uint2*)pxl, n4);
        n4 = (C3D * Dm) / 4;
        conv_hl_kernel<<<(n4 + 255) / 256, 256>>>((const float4*)in_w, (uint2*)pwih, (uint2*)pwil, n4);
        n4 = (Dm * Dm) / 4;
        conv_hl_kernel<<<(n4 + 255) / 256, 256>>>((const float4*)out_w, (uint2*)pwoh, (uint2*)pwol, n4);
    }

    // 1) in_proj GEMM: (8192,2048) @ (2048,6144)^T + bias -> g_U (b,l,c)
    mma_gemm<<<dim3(C3D/128, (Bn*Lseq)/128), 256, GEMM_SMEM>>>(
        pxh, pxl, pwih, pwil, in_b, pU, Bn*Lseq, C3D, Dm);

    // 2) short conv + split + gate -> g_VG, g_X0
    shortconv_kernel<<<dim3(Lseq/64, Dm/32, Bn), 256>>>(pU, short_w, short_b, pVG, pX0);

    // 3) filter synthesis
    filter_h_kernel<<<Lseq/256, 256>>>(w0, b0, freq, w1, b1, w2, b2);
    filter_k_kernel<<<dim3(Dm/64, Lseq/64), 256>>>(w3);

    // 4) radix-4 FFT causal conv + gating -> g_Y (b,d,l)
    fftconv_kernel<<<Dm, 512, 163840>>>(pVG, pX0, pK, fbias, pY);

    // 5) transpose Y (b,d,l) -> (b,l,d), fused bf16 hi/lo split
    transpose_hl_kernel<<<dim3(Lseq/32, Dm/32, Bn), 256>>>(pY, pyth, pytl);

    // 6) out_proj GEMM: (8192,2048) @ (2048,2048)^T + bias -> out (b,l,d)
    mma_gemm<<<dim3(Dm/128, (Bn*Lseq)/128), 256, GEMM_SMEM>>>(
        pyth, pytl, pwoh, pwol, out_b, out, Bn*Lseq, Dm, Dm);
}

// round 16
// speedup vs baseline: 1.5339x; 1.5339x over previous
#include <cuda_runtime.h>
#include <cuda_bf16.h>
#include <math.h>
#include <stdint.h>

#define Bn      2
#define Dm      2048
#define Lseq    4096
#define C3D     6144
#define NF      8192
#define HF      4096
#define FO      64

// ------------------- scratch (device globals: no allocs allowed) -------------------
__device__ float g_U [(size_t)Bn * Lseq * C3D];   // in_proj output, (b, l, c)
__device__ float g_VG[(size_t)Bn * Dm * Lseq];    // v * x1, (b, d, l)
__device__ float g_X0[(size_t)Bn * Dm * Lseq];    // x0 gate, (b, d, l)
__device__ float g_H [(size_t)Lseq * FO];         // MLP features (l, j)
__device__ float g_K [(size_t)Dm * Lseq];         // filter k (d, l)
__device__ float g_Y [(size_t)Bn * Dm * Lseq];    // gated conv output, (b, d, l)

// bf16 hi/lo split operands for tensor-core GEMMs
__device__ __nv_bfloat16 g_xh [(size_t)Bn * Lseq * Dm];
__device__ __nv_bfloat16 g_xl [(size_t)Bn * Lseq * Dm];
__device__ __nv_bfloat16 g_wih[(size_t)C3D * Dm];
__device__ __nv_bfloat16 g_wil[(size_t)C3D * Dm];
__device__ __nv_bfloat16 g_woh[(size_t)Dm * Dm];
__device__ __nv_bfloat16 g_wol[(size_t)Dm * Dm];
__device__ __nv_bfloat16 g_yth[(size_t)Bn * Lseq * Dm];
__device__ __nv_bfloat16 g_ytl[(size_t)Bn * Lseq * Dm];

// ------------------- PTX helpers (all legal on compute_103 virtual arch) -------------------
__device__ __forceinline__ uint32_t smem_u32(const void* p) {
    uint32_t a;
    asm("{ .reg .u64 t; cvta.to.shared.u64 t, %1; cvt.u32.u64 %0, t; }" : "=r"(a) : "l"(p));
    return a;
}
__device__ __forceinline__ void cp_async16(uint32_t s, const void* g) {
    asm volatile("cp.async.cg.shared.global [%0], [%1], 16;" :: "r"(s), "l"(g));
}
__device__ __forceinline__ void cp_commit() {
    asm volatile("cp.async.commit_group;");
}
template<int N> __device__ __forceinline__ void cp_wait() {
    asm volatile("cp.async.wait_group %0;" :: "n"(N));
}
__device__ __forceinline__ void ldmx4(uint32_t a, uint32_t* r) {
    asm volatile("ldmatrix.sync.aligned.m8n8.x4.shared.b16 {%0,%1,%2,%3}, [%4];"
                 : "=r"(r[0]), "=r"(r[1]), "=r"(r[2]), "=r"(r[3]) : "r"(a));
}
__device__ __forceinline__ void mma16816(float* d, const uint32_t* a, const uint32_t* b) {
    asm volatile(
        "mma.sync.aligned.m16n8k16.row.col.f32.bf16.bf16.f32 "
        "{%0,%1,%2,%3}, {%4,%5,%6,%7}, {%8,%9}, {%0,%1,%2,%3};"
        : "+f"(d[0]), "+f"(d[1]), "+f"(d[2]), "+f"(d[3])
        : "r"(a[0]), "r"(a[1]), "r"(a[2]), "r"(a[3]), "r"(b[0]), "r"(b[1]));
}
__device__ __forceinline__ uint32_t bf2u(__nv_bfloat162 h) {
    return *reinterpret_cast<uint32_t*>(&h);
}

// ------------------- fp32 -> bf16 hi/lo split (elementwise) -------------------
__global__ __launch_bounds__(256) void conv_hl_kernel(
    const float4* __restrict__ in, uint2* __restrict__ h, uint2* __restrict__ l, int n4)
{
    int i = blockIdx.x * 256 + threadIdx.x;
    if (i >= n4) return;
    float4 v = in[i];
    __nv_bfloat162 h01 = __float22bfloat162_rn(make_float2(v.x, v.y));
    __nv_bfloat162 h23 = __float22bfloat162_rn(make_float2(v.z, v.w));
    float2 f01 = __bfloat1622float2(h01);
    float2 f23 = __bfloat1622float2(h23);
    __nv_bfloat162 l01 = __float22bfloat162_rn(make_float2(v.x - f01.x, v.y - f01.y));
    __nv_bfloat162 l23 = __float22bfloat162_rn(make_float2(v.z - f23.x, v.w - f23.y));
    h[i] = make_uint2(bf2u(h01), bf2u(h23));
    l[i] = make_uint2(bf2u(l01), bf2u(l23));
}

// ------------------- split-bf16 HMMA GEMM (exact R9 winner) -------------------
// C[m,n] = sum_k A[m,k]*Bw[n,k] + bias[n] with A ~ Ah+Al, Bw ~ Bh+Bl (bf16).
// BM=BN=128, BK=32, 8 warps (2m x 4n), warp tile 64x32, 2-stage cp.async pipeline,
// 81920B smem/CTA -> 2 CTAs/SM. Stage (40960B): Ah[128x32 pad80], Al, Bh, Bl.
__global__ __launch_bounds__(256, 2) void mma_gemm(
    const __nv_bfloat16* __restrict__ Ah, const __nv_bfloat16* __restrict__ Al,
    const __nv_bfloat16* __restrict__ Bh, const __nv_bfloat16* __restrict__ Bl,
    const float* __restrict__ bias, float* __restrict__ C,
    int M, int N, int K)
{
    extern __shared__ char sm[];
    uint32_t smb = smem_u32(sm);
    int tid = threadIdx.x, lid = tid & 31, wid = tid >> 5;
    int wm = wid & 1, wn = wid >> 1;
    int m0 = blockIdx.y * 128, n0 = blockIdx.x * 128;

    const __nv_bfloat16* pAh = Ah + (size_t)m0 * K;
    const __nv_bfloat16* pAl = Al + (size_t)m0 * K;
    const __nv_bfloat16* pBh = Bh + (size_t)n0 * K;
    const __nv_bfloat16* pBl = Bl + (size_t)n0 * K;
    const int nch = K >> 5;

    auto issue = [&](int c) {
        uint32_t sb = smb + (uint32_t)(c & 1) * 40960u;
        #pragma unroll
        for (int t = 0; t < 2; t++) {
            int e = tid + t * 256;
            int row = e >> 2, seg = e & 3;
            size_t go = (size_t)row * K + (size_t)c * 32 + seg * 8;
            uint32_t so = (uint32_t)row * 80u + (uint32_t)seg * 16u;
            cp_async16(sb + so,           pAh + go);
            cp_async16(sb + 10240u + so,  pAl + go);
            cp_async16(sb + 20480u + so,  pBh + go);
            cp_async16(sb + 30720u + so,  pBl + go);
        }
    };

    issue(0); cp_commit();
    if (nch > 1) { issue(1); cp_commit(); }

    float acc[4][4][4];
    #pragma unroll
    for (int mi = 0; mi < 4; mi++)
        #pragma unroll
        for (int ni = 0; ni < 4; ni++)
            #pragma unroll
            for (int q = 0; q < 4; q++) acc[mi][ni][q] = 0.f;

    uint32_t aOff = (uint32_t)(wm * 64 + (lid & 15)) * 80u + (uint32_t)(lid >> 4) * 16u;
    // B ldmx4 lane mapping: row-in-tile = lid&7, +8 rows if lid>=16, k-half if bit3
    uint32_t bOff = 20480u
                  + (uint32_t)(wn * 32 + (lid & 7) + ((lid >> 4) & 1) * 8) * 80u
                  + (uint32_t)((lid >> 3) & 1) * 16u;

    for (int c = 0; c < nch; c++) {
        cp_wait<1>();
        __syncthreads();
        uint32_t sb = smb + (uint32_t)(c & 1) * 40960u;
        #pragma unroll
        for (int ks = 0; ks < 2; ks++) {
            uint32_t ah[4][4], al[4][4], bh[4][2], bl[4][2];
            // B fragments first (small; latency hides under A loads + MMAs)
            #pragma unroll
            for (int p = 0; p < 2; p++) {
                uint32_t a = sb + bOff + (uint32_t)p * 1280u + (uint32_t)ks * 32u;
                uint32_t r[4];
                ldmx4(a, r);
                bh[2*p][0] = r[0]; bh[2*p][1] = r[1]; bh[2*p+1][0] = r[2]; bh[2*p+1][1] = r[3];
                ldmx4(a + 10240u, r);
                bl[2*p][0] = r[0]; bl[2*p][1] = r[1]; bl[2*p+1][0] = r[2]; bl[2*p+1][1] = r[3];
            }
            #pragma unroll
            for (int mi = 0; mi < 4; mi++) {
                uint32_t a = sb + aOff + (uint32_t)mi * 1280u + (uint32_t)ks * 32u;
                ldmx4(a, ah[mi]);
                ldmx4(a + 10240u, al[mi]);
            }
            // interleaved order (R9 winner): ptxas handles scheduling best
            #pragma unroll
            for (int mi = 0; mi < 4; mi++)
                #pragma unroll
                for (int ni = 0; ni < 4; ni++) {
                    mma16816(acc[mi][ni], ah[mi], bh[ni]);
                    mma16816(acc[mi][ni], ah[mi], bl[ni]);
                    mma16816(acc[mi][ni], al[mi], bh[ni]);
                }
        }
        __syncthreads();
        if (c + 2 < nch) issue(c + 2);
        cp_commit();
    }

    // epilogue
    #pragma unroll
    for (int mi = 0; mi < 4; mi++) {
        int r = m0 + wm * 64 + mi * 16 + (lid >> 2);
        #pragma unroll
        for (int ni = 0; ni < 4; ni++) {
            int cc = n0 + wn * 32 + ni * 8 + (lid & 3) * 2;
            float2 bv = *(const float2*)(bias + cc);
            float2 o0 = make_float2(acc[mi][ni][0] + bv.x, acc[mi][ni][1] + bv.y);
            float2 o1 = make_float2(acc[mi][ni][2] + bv.x, acc[mi][ni][3] + bv.y);
            *(float2*)(C + (size_t)r * N + cc)       = o0;
            *(float2*)(C + (size_t)(r + 8) * N + cc) = o1;
        }
    }
}

// ------------------- transpose (b,d,l) -> (b,l,d), fused bf16 hi/lo split -------------------
__global__ __launch_bounds__(256) void transpose_hl_kernel(
    const float* __restrict__ Y, __nv_bfloat16* __restrict__ Th, __nv_bfloat16* __restrict__ Tl)
{
    __shared__ float ts[32][33];
    int b = blockIdx.z;
    int d0 = blockIdx.y * 32, l0 = blockIdx.x * 32;
    int c = threadIdx.x & 31, r0 = threadIdx.x >> 5;
    #pragma unroll
    for (int p = 0; p < 4; p++) {
        int r = r0 + p * 8;
        ts[r][c] = Y[((size_t)b * Dm + d0 + r) * Lseq + l0 + c];
    }
    __syncthreads();
    #pragma unroll
    for (int p = 0; p < 4; p++) {
        int r = r0 + p * 8;
        float v = ts[c][r];
        __nv_bfloat16 h = __float2bfloat16_rn(v);
        __nv_bfloat16 l = __float2bfloat16_rn(v - __bfloat162float(h));
        size_t o = ((size_t)b * Lseq + l0 + r) * Dm + d0 + c;
        Th[o] = h;
        Tl[o] = l;
    }
}

// ------------------- complex helpers -------------------
__device__ __forceinline__ float2 cadd(float2 a, float2 b) { return make_float2(a.x+b.x, a.y+b.y); }
__device__ __forceinline__ float2 csub(float2 a, float2 b) { return make_float2(a.x-b.x, a.y-b.y); }
__device__ __forceinline__ float2 cmul(float2 a, float2 b) {
    return make_float2(a.x*b.x - a.y*b.y, a.x*b.y + a.y*b.x);
}
__device__ __forceinline__ float2 cmulc(float2 a, float2 b) {  // a * conj(b)
    return make_float2(a.x*b.x + a.y*b.y, a.y*b.x - a.x*b.y);
}

// ------------------- short depthwise conv (K=3, causal) + split + gate -------------------
__global__ __launch_bounds__(256) void shortconv_kernel(
    const float* __restrict__ U, const float* __restrict__ sw,
    const float* __restrict__ sb, float* __restrict__ VG, float* __restrict__ X0)
{
    __shared__ float su[3][66][33];
    int tid = threadIdx.x;
    int b = blockIdx.z, d0 = blockIdx.y * 32, l0 = blockIdx.x * 64;

    for (int idx = tid; idx < 3*66*32; idx += 256) {
        int d = idx & 31;
        int rest = idx >> 5;
        int x = rest % 66;
        int g = rest / 66;
        int l = l0 - 2 + x;
        float v = 0.f;
        if (l >= 0) v = U[((size_t)b * Lseq + l) * C3D + g * Dm + d0 + d];
        su[g][x][d] = v;
    }
    __syncthreads();

    int l = tid & 63;
    int dq = tid >> 6;
    #pragma unroll
    for (int p = 0; p < 8; p++) {
        int dloc = dq + (p << 2);
        int c0 = d0 + dloc;
        float r[3];
        #pragma unroll
        for (int g = 0; g < 3; g++) {
            int c = g * Dm + c0;
            float w0 = sw[c*3+0], w1 = sw[c*3+1], w2 = sw[c*3+2];
            r[g] = w0 * su[g][l][dloc] + w1 * su[g][l+1][dloc] + w2 * su[g][l+2][dloc] + sb[c];
        }
        size_t o = ((size_t)b * Dm + c0) * Lseq + l0 + l;
        X0[o] = r[0];
        VG[o] = r[2] * r[1];
    }
}

// ------------------- filter MLP features h (L, 64) -------------------
__global__ __launch_bounds__(256) void filter_h_kernel(
    const float* __restrict__ w0, const float* __restrict__ b0,
    const float* __restrict__ freq,
    const float* __restrict__ w1, const float* __restrict__ b1,
    const float* __restrict__ w2, const float* __restrict__ b2)
{
    int l = blockIdx.x * blockDim.x + threadIdx.x;
    if (l >= Lseq) return;
    const float PI2 = 6.2831853071795864769f;
    float t  = (float)l / (float)(Lseq - 1);
    float wl = PI2 * (float)l / (float)Lseq;
    float ang = 1e-4f * wl;
    float z0 = t, z1 = cosf(ang), z2 = -sinf(ang);

    float h0[FO], h1[FO], h2[FO];
    #pragma unroll
    for (int j = 0; j < FO; j++) {
        float s = w0[j*3+0]*z0 + w0[j*3+1]*z1 + w0[j*3+2]*z2 + b0[j];
        h0[j] = sinf(freq[j] * s);
    }
    #pragma unroll
    for (int j = 0; j < FO; j++) {
        float s = b1[j];
        #pragma unroll
        for (int q = 0; q < FO; q++) s += h0[q] * w1[j*FO+q];
        h1[j] = sinf(freq[j] * s);
    }
    #pragma unroll
    for (int j = 0; j < FO; j++) {
        float s = b2[j];
        #pragma unroll
        for (int q = 0; q < FO; q++) s += h1[q] * w2[j*FO+q];
        h2[j] = sinf(freq[j] * s);
    }
    #pragma unroll
    for (int j = 0; j < FO; j++) g_H[(size_t)l*FO + j] = h2[j];
}

// ------------------- filter k(d,l) = (h @ w3^T) * decay, register-blocked -------------------
__global__ __launch_bounds__(256) void filter_k_kernel(const float* __restrict__ w3)
{
    __shared__ float HtT[FO][66];    // HtT[j][l_local]
    __shared__ float W3T[FO][68];    // W3T[j][d_local]
    int d0 = blockIdx.x * 64, l0 = blockIdx.y * 64;
    int tid = threadIdx.x;

    for (int idx = tid; idx < 64*FO; idx += 256) {
        int l = idx >> 6, j = idx & 63;
        HtT[j][l] = g_H[(size_t)(l0 + l)*FO + j];
    }
    for (int idx = tid; idx < 64*FO; idx += 256) {
        int d = idx >> 6, j = idx & 63;
        W3T[j][d] = w3[(size_t)(d0 + d)*FO + j];
    }
    __syncthreads();

    int lg = tid >> 3;   // 0..31 -> 2 l's each
    int dg = tid & 7;    // 0..7  -> 8 d's each
    float acc[2][8];
    #pragma unroll
    for (int a = 0; a < 2; a++)
        #pragma unroll
        for (int b = 0; b < 8; b++) acc[a][b] = 0.f;

    #pragma unroll 4
    for (int j = 0; j < FO; j++) {
        float2 h2v = *(const float2*)&HtT[j][lg*2];
        float4 wv0 = *(const float4*)&W3T[j][dg*8];
        float4 wv1 = *(const float4*)&W3T[j][dg*8 + 4];
        float wv[8] = {wv0.x, wv0.y, wv0.z, wv0.w, wv1.x, wv1.y, wv1.z, wv1.w};
        float hv[2] = {h2v.x, h2v.y};
        #pragma unroll
        for (int a = 0; a < 2; a++)
            #pragma unroll
            for (int b = 0; b < 8; b++) acc[a][b] += hv[a] * wv[b];
    }

    const float MIN_DEC = -3.0701134573253944f;   // log(0.01)/1.5
    const float MAX_DEC = -15.350567286626972f;   // log(0.01)/0.3
    #pragma unroll
    for (int a = 0; a < 2; a++) {
        int l = l0 + lg*2 + a;
        float t = (float)l / (float)(Lseq - 1);
        #pragma unroll
        for (int b = 0; b < 8; b++) {
            int d = d0 + dg*8 + b;
            float delta = MIN_DEC + (MAX_DEC - MIN_DEC) * ((float)d / (float)(Dm - 1));
            float decay = __expf(-t * fabsf(delta));
            g_K[(size_t)d * Lseq + l] = acc[a][b] * decay;
        }
    }
}

// ------------------- radix-4 FFT causal conv, fused gating -------------------
// Forward DIF (natural -> base-4-digit-reversed), product in permuted order,
// inverse DIT (permuted -> natural). First fwd stage folded into zero-padded
// load; last inv stage folded into epilogue; middle (final fwd radix-2 of
// W and KF + pointwise product + first inverse radix-2) fused into ONE pass.

template<int M>
__device__ __forceinline__ void r4f(float2* X, const float2* TW, int tid)
{
    const int T = 2048 / M;
    #pragma unroll
    for (int it = 0; it < 4; it++) {
        int i = tid + it * 512;
        int j = i & (M - 1);
        int b0 = (i / M) * (4 * M) + j;
        float2 a = X[b0], b = X[b0 + M], c = X[b0 + 2*M], d = X[b0 + 3*M];
        float2 s0 = cadd(a, c), s1 = csub(a, c);
        float2 s2 = cadd(b, d), s3 = csub(b, d);
        float2 t3 = make_float2(s3.y, -s3.x);           // -i * s3
        float2 w1 = TW[j * T], w2 = TW[2 * j * T];
        float2 w3 = cmul(w1, w2);
        X[b0]       = cadd(s0, s2);
        X[b0 + M]   = cmul(cadd(s1, t3), w1);
        X[b0 + 2*M] = cmul(csub(s0, s2), w2);
        X[b0 + 3*M] = cmul(csub(s1, t3), w3);
    }
    __syncthreads();
}

template<int M>
__device__ __forceinline__ void r4i(float2* X, const float2* TW, int tid)
{
    const int T = 2048 / M;
    #pragma unroll
    for (int it = 0; it < 4; it++) {
        int i = tid + it * 512;
        int j = i & (M - 1);
        int b0 = (i / M) * (4 * M) + j;
        float2 w1 = TW[j * T], w2 = TW[2 * j * T];
        float2 w3 = cmul(w1, w2);
        float2 u0 = X[b0];
        float2 u1 = cmulc(X[b0 + M],   w1);
        float2 u2 = cmulc(X[b0 + 2*M], w2);
        float2 u3 = cmulc(X[b0 + 3*M], w3);
        float2 p0 = cadd(u0, u2), p1 = csub(u0, u2);
        float2 q0 = cadd(u1, u3), q1 = csub(u1, u3);
        float2 iq1 = make_float2(-q1.y, q1.x);          // +i * q1
        X[b0]       = cadd(p0, q0);
        X[b0 + M]   = cadd(p1, iq1);
        X[b0 + 2*M] = csub(p0, q0);
        X[b0 + 3*M] = csub(p1, iq1);
    }
    __syncthreads();
}

__global__ __launch_bounds__(512) void fftconv_kernel(
    const float* __restrict__ VG, const float* __restrict__ X0g,
    const float* __restrict__ Kf, const float* __restrict__ fbias,
    float* __restrict__ Y)
{
    extern __shared__ float2 smf[];
    float2* W  = smf;                // 8192
    float2* KF = smf + NF;           // 8192
    float2* TW = smf + 2*NF;         // 4096

    int d = blockIdx.x, tid = threadIdx.x;

    for (int j = tid; j < HF; j += 512) {
        float s, c;
        sincosf(-6.283185307179586f * ((float)j * (1.0f / (float)NF)), &s, &c);
        TW[j] = make_float2(c, s);
    }
    __syncthreads();

    // load + first forward radix-4 stage (span 2048; upper half zero)
    const float* kd  = Kf + (size_t)d * Lseq;
    const float* vg0 = VG + (size_t)d * Lseq;
    const float* vg1 = VG + ((size_t)Dm + d) * Lseq;
    for (int j = tid; j < 2048; j += 512) {
        float2 w1 = TW[j], w2 = TW[2*j];
        float2 w3 = cmul(w1, w2);
        float k0 = kd[j], k1 = kd[j + 2048];
        KF[j]        = make_float2(k0 + k1, 0.f);
        KF[j + 2048] = cmul(make_float2(k0, -k1), w1);
        KF[j + 4096] = make_float2((k0 - k1) * w2.x, (k0 - k1) * w2.y);
        KF[j + 6144] = cmul(make_float2(k0, k1), w3);
        float2 a0 = make_float2(vg0[j], vg1[j]);
        float2 a1 = make_float2(vg0[j + 2048], vg1[j + 2048]);
        float2 mia1 = make_float2(a1.y, -a1.x);   // -i*a1
        float2 pia1 = make_float2(-a1.y, a1.x);   // +i*a1
        W[j]        = cadd(a0, a1);
        W[j + 2048] = cmul(cadd(a0, mia1), w1);
        W[j + 4096] = cmul(csub(a0, a1), w2);
        W[j + 6144] = cmul(cadd(a0, pia1), w3);
    }
    __syncthreads();

    // forward radix-4 stages (KF then W); final radix-2 deferred to fused middle
    r4f<512>(KF, TW, tid); r4f<128>(KF, TW, tid); r4f<32>(KF, TW, tid);
    r4f<8>(KF, TW, tid);   r4f<2>(KF, TW, tid);

    r4f<512>(W, TW, tid); r4f<128>(W, TW, tid); r4f<32>(W, TW, tid);
    r4f<8>(W, TW, tid);   r4f<2>(W, TW, tid);

    // FUSED middle: final fwd radix-2 (W and KF, in registers) + pointwise
    // product + first inverse radix-2 — one smem pass instead of four.
    #pragma unroll
    for (int it = 0; it < 8; it++) {
        int i = tid + it * 512;
        int b = i << 1;
        float2 a = W[b], c = W[b + 1];
        float2 u = cadd(a, c), v = csub(a, c);
        float2 ka = KF[b], kc = KF[b + 1];
        float2 k0 = cadd(ka, kc), k1 = csub(ka, kc);
        float2 p0 = cmul(u, k0), p1 = cmul(v, k1);
        W[b]     = cadd(p0, p1);
        W[b + 1] = csub(p0, p1);
    }
    __syncthreads();

    // inverse radix-4 stages
    r4i<2>(W, TW, tid);  r4i<8>(W, TW, tid);   r4i<32>(W, TW, tid);
    r4i<128>(W, TW, tid); r4i<512>(W, TW, tid);

    // final inverse stage (span 2048) fused with gating epilogue
    float bd = fbias[d];
    const float* x00 = X0g + (size_t)d * Lseq;
    const float* x01 = X0g + ((size_t)Dm + d) * Lseq;
    float* y0 = Y + (size_t)d * Lseq;
    float* y1 = Y + ((size_t)Dm + d) * Lseq;
    const float inv = 1.0f / (float)NF;
    for (int j = tid; j < 2048; j += 512) {
        float2 w1 = TW[j], w2 = TW[2*j];
        float2 w3 = cmul(w1, w2);
        float2 u0 = W[j];
        float2 u1 = cmulc(W[j + 2048], w1);
        float2 u2 = cmulc(W[j + 4096], w2);
        float2 u3 = cmulc(W[j + 6144], w3);
        float2 x0v = cadd(cadd(u0, u1), cadd(u2, u3));
        float2 p1 = csub(u0, u2), q1 = csub(u1, u3);
        float2 x1v = make_float2(p1.x - q1.y, p1.y + q1.x);
        int l0i = j, l1i = j + 2048;
        y0[l0i] = (x0v.x * inv + vg0[l0i] * bd) * x00[l0i];
        y1[l0i] = (x0v.y * inv + vg1[l0i] * bd) * x01[l0i];
        y0[l1i] = (x1v.x * inv + vg0[l1i] * bd) * x00[l1i];
        y1[l1i] = (x1v.y * inv + vg1[l1i] * bd) * x01[l1i];
    }
}

// ------------------- launch -------------------
extern "C" void kernel_launch(void* const* d_in, const int* in_sizes, int n_in,
                              void* d_out, int out_size)
{
    const float* x       = (const float*)d_in[0];
    const float* in_w    = (const float*)d_in[1];
    const float* in_b    = (const float*)d_in[2];
    const float* short_w = (const float*)d_in[3];
    const float* short_b = (const float*)d_in[4];
    const float* w0      = (const float*)d_in[5];
    const float* b0      = (const float*)d_in[6];
    const float* freq    = (const float*)d_in[7];
    const float* w1      = (const float*)d_in[8];
    const float* b1      = (const float*)d_in[9];
    const float* w2      = (const float*)d_in[10];
    const float* b2      = (const float*)d_in[11];
    const float* w3      = (const float*)d_in[12];
    const float* fbias   = (const float*)d_in[13];
    const float* out_w   = (const float*)d_in[14];
    const float* out_b   = (const float*)d_in[15];
    float* out = (float*)d_out;

    float *pU, *pVG, *pX0, *pK, *pY;
    __nv_bfloat16 *pxh, *pxl, *pwih, *pwil, *pwoh, *pwol, *pyth, *pytl;
    cudaGetSymbolAddress((void**)&pU,   g_U);
    cudaGetSymbolAddress((void**)&pVG,  g_VG);
    cudaGetSymbolAddress((void**)&pX0,  g_X0);
    cudaGetSymbolAddress((void**)&pK,   g_K);
    cudaGetSymbolAddress((void**)&pY,   g_Y);
    cudaGetSymbolAddress((void**)&pxh,  g_xh);
    cudaGetSymbolAddress((void**)&pxl,  g_xl);
    cudaGetSymbolAddress((void**)&pwih, g_wih);
    cudaGetSymbolAddress((void**)&pwil, g_wil);
    cudaGetSymbolAddress((void**)&pwoh, g_woh);
    cudaGetSymbolAddress((void**)&pwol, g_wol);
    cudaGetSymbolAddress((void**)&pyth, g_yth);
    cudaGetSymbolAddress((void**)&pytl, g_ytl);

    const int GEMM_SMEM = 2 * 40960;   // 81920 -> 2 CTAs/SM
    cudaFuncSetAttribute(mma_gemm, cudaFuncAttributeMaxDynamicSharedMemorySize, GEMM_SMEM);
    cudaFuncSetAttribute(fftconv_kernel, cudaFuncAttributeMaxDynamicSharedMemorySize, 163840);

    // 0) split fp32 -> bf16 hi/lo for GEMM operands
    {
        int n4;
        n4 = (Bn * Lseq * Dm) / 4;
        conv_hl_kernel<<<(n4 + 255) / 256, 256>>>((const float4*)x, (uint2*)pxh, (uint2*)pxl, n4);
        n4 = (C3D * Dm) / 4;
        conv_hl_kernel<<<(n4 + 255) / 256, 256>>>((const float4*)in_w, (uint2*)pwih, (uint2*)pwil, n4);
        n4 = (Dm * Dm) / 4;
        conv_hl_kernel<<<(n4 + 255) / 256, 256>>>((const float4*)out_w, (uint2*)pwoh, (uint2*)pwol, n4);
    }

    // 1) in_proj GEMM: (8192,2048) @ (2048,6144)^T + bias -> g_U (b,l,c)
    mma_gemm<<<dim3(C3D/128, (Bn*Lseq)/128), 256, GEMM_SMEM>>>(
        pxh, pxl, pwih, pwil, in_b, pU, Bn*Lseq, C3D, Dm);

    // 2) short conv + split + gate -> g_VG, g_X0
    shortconv_kernel<<<dim3(Lseq/64, Dm/32, Bn), 256>>>(pU, short_w, short_b, pVG, pX0);

    // 3) filter synthesis
    filter_h_kernel<<<Lseq/256, 256>>>(w0, b0, freq, w1, b1, w2, b2);
    filter_k_kernel<<<dim3(Dm/64, Lseq/64), 256>>>(w3);

    // 4) radix-4 FFT causal conv + gating -> g_Y (b,d,l)
    fftconv_kernel<<<Dm, 512, 163840>>>(pVG, pX0, pK, fbias, pY);

    // 5) transpose Y (b,d,l) -> (b,l,d), fused bf16 hi/lo split
    transpose_hl_kernel<<<dim3(Lseq/32, Dm/32, Bn), 256>>>(pY, pyth, pytl);

    // 6) out_proj GEMM: (8192,2048) @ (2048,2048)^T + bias -> out (b,l,d)
    mma_gemm<<<dim3(Dm/128, (Bn*Lseq)/128), 256, GEMM_SMEM>>>(
        pyth, pytl, pwoh, pwol, out_b, out, Bn*Lseq, Dm, Dm);
}